// round 2
// baseline (speedup 1.0000x reference)
#include <cuda_runtime.h>

#define NB 256
#define NQ 1000
#define NC 80
#define NN 80000          // NQ * NC per batch
#define TOPK 300
#define NT 1024
#define GSIZE 4096        // fallback group size
#define CAP 6144          // candidate buffer entries (u64)
#define LISTCAP 2048
#define HBINS 2048
#define TSAMP 64          // sample-rank target for streaming threshold
#define TSEL 384          // fallback selection rank

// ---------- monotone float<->uint mapping (handles negatives) ----------
__device__ __forceinline__ unsigned flipf(unsigned b) {
    return (b & 0x80000000u) ? ~b : (b | 0x80000000u);
}
__device__ __forceinline__ unsigned unflipf(unsigned u) {
    return (u & 0x80000000u) ? (u & 0x7FFFFFFFu) : ~u;
}

// ---------- sigmoid matching XLA: logistic(x) = 0.5 + 0.5*tanh(0.5*x) ----------
__device__ __forceinline__ float sigmoid_ref(float x) {
    float hx = __fmul_rn(0.5f, x);
    float ax = fabsf(hx);
    float xc = fminf(fmaxf(hx, -9.0f), 9.0f);
    float x2 = __fmul_rn(xc, xc);
    float p = -2.76076847742355e-16f;
    p = fmaf(x2, p, 2.00018790482477e-13f);
    p = fmaf(x2, p, -8.60467152213735e-11f);
    p = fmaf(x2, p, 5.12229709037114e-08f);
    p = fmaf(x2, p, 1.48572235717979e-05f);
    p = fmaf(x2, p, 6.37261928875436e-04f);
    p = fmaf(x2, p, 4.89352455891786e-03f);
    p = __fmul_rn(xc, p);
    float q = 1.19825839466702e-06f;
    q = fmaf(x2, q, 1.18534705686654e-04f);
    q = fmaf(x2, q, 2.26843463243900e-03f);
    q = fmaf(x2, q, 4.89352518554385e-03f);
    float t = __fdiv_rn(p, q);
    t = (ax < 4e-4f) ? hx : t;
    return __fadd_rn(__fmul_rn(0.5f, t), 0.5f);
}

// ---------- warp-aggregated append ----------
__device__ __forceinline__ void append_key(unsigned long long* buf, int* cnt,
                                           unsigned ub, unsigned idx) {
    unsigned long long key = ((unsigned long long)ub << 32) | idx;
    unsigned mask = __activemask();
    int lane = threadIdx.x & 31;
    int leader = __ffs(mask) - 1;
    int pos = 0;
    if (lane == leader) pos = atomicAdd(cnt, __popc(mask));
    pos = __shfl_sync(mask, pos, leader) + __popc(mask & ((1u << lane) - 1u));
    if (pos < CAP) buf[pos] = key;
}

// ---------- fallback histogram radix-select (never taken on normal data) ----------
__device__ void run_select(unsigned long long* buf, unsigned long long* lst,
                           unsigned* hist, int* sc, int n, int target) {
    const int tid = threadIdx.x;
    if (n <= target) {
        if (tid == 0) { sc[0] = 0; sc[1] = 0; sc[2] = 0; sc[3] = n; }
        __syncthreads();
        for (int i = tid; i < n; i += NT) lst[i] = buf[i];
        __syncthreads();
        return;
    }
    for (int i = tid; i < HBINS; i += NT) hist[i] = 0;
    __syncthreads();
    for (int i = tid; i < n; i += NT)
        atomicAdd(&hist[(unsigned)(buf[i] >> 53)], 1u);
    __syncthreads();
    for (int off = 1; off < HBINS; off <<= 1) {
        unsigned v0 = (tid + off < HBINS) ? hist[tid + off] : 0u;
        unsigned v1 = (tid + NT + off < HBINS) ? hist[tid + NT + off] : 0u;
        __syncthreads();
        hist[tid] += v0;
        hist[tid + NT] += v1;
        __syncthreads();
    }
    for (int i = tid; i < HBINS; i += NT) {
        unsigned s = hist[i];
        unsigned sn = (i + 1 < HBINS) ? hist[i + 1] : 0u;
        if (s >= (unsigned)target && sn < (unsigned)target) { sc[0] = i; sc[4] = (int)sn; }
    }
    if (tid == 0) { sc[2] = 0; sc[3] = 0; }
    __syncthreads();
    const int B = sc[0];
    const int nAbove = sc[4];
    const int selcount = (int)hist[B];
    int refined = 0, B2 = 0;
    if (selcount > 1024) {
        __syncthreads();
        for (int i = tid; i < HBINS; i += NT) hist[i] = 0;
        __syncthreads();
        for (int i = tid; i < n; i += NT) {
            unsigned long long k = buf[i];
            if ((unsigned)(k >> 53) == (unsigned)B)
                atomicAdd(&hist[(unsigned)(k >> 42) & 0x7FFu], 1u);
        }
        __syncthreads();
        for (int off = 1; off < HBINS; off <<= 1) {
            unsigned v0 = (tid + off < HBINS) ? hist[tid + off] : 0u;
            unsigned v1 = (tid + NT + off < HBINS) ? hist[tid + NT + off] : 0u;
            __syncthreads();
            hist[tid] += v0;
            hist[tid + NT] += v1;
            __syncthreads();
        }
        int extra = target - nAbove;
        for (int i = tid; i < HBINS; i += NT) {
            unsigned s = hist[i];
            unsigned sn = (i + 1 < HBINS) ? hist[i + 1] : 0u;
            if (s >= (unsigned)extra && sn < (unsigned)extra) sc[1] = i;
        }
        if (tid == 0) sc[2] = 1;
        __syncthreads();
        refined = 1;
        B2 = sc[1];
    }
    for (int i = tid; i < n; i += NT) {
        unsigned long long k = buf[i];
        unsigned bin = (unsigned)(k >> 53);
        bool sel = (bin > (unsigned)B) ||
                   (bin == (unsigned)B &&
                    (!refined || (((unsigned)(k >> 42) & 0x7FFu) >= (unsigned)B2)));
        if (sel) {
            int p = atomicAdd(&sc[3], 1);
            if (p < LISTCAP) lst[p] = k;
        }
    }
    __syncthreads();
}

extern "C" __global__ void __launch_bounds__(NT, 2)
postproc_kernel(const float* __restrict__ logits,
                const float* __restrict__ boxes,
                float* __restrict__ out) {
    extern __shared__ unsigned char smem_raw[];
    unsigned long long* buf = reinterpret_cast<unsigned long long*>(smem_raw);
    unsigned long long* lst = buf + CAP;
    unsigned* hist = reinterpret_cast<unsigned*>(lst + LISTCAP);
    __shared__ int s_count;
    __shared__ int s_bin;
    __shared__ int sc[5];

    const int tid = threadIdx.x;
    const int b = blockIdx.x;
    const float* Lp = logits + (size_t)b * NN;

    // ---------------- phase 1: threshold from first 4096 elements ----------------
    for (int i = tid; i < HBINS; i += NT) hist[i] = 0;
    if (tid == 0) { s_count = 0; s_bin = 0; }
    __syncthreads();
    {
        float4 v = *reinterpret_cast<const float4*>(Lp + tid * 4);
        atomicAdd(&hist[flipf(__float_as_uint(v.x)) >> 21], 1u);
        atomicAdd(&hist[flipf(__float_as_uint(v.y)) >> 21], 1u);
        atomicAdd(&hist[flipf(__float_as_uint(v.z)) >> 21], 1u);
        atomicAdd(&hist[flipf(__float_as_uint(v.w)) >> 21], 1u);
    }
    __syncthreads();
    for (int off = 1; off < HBINS; off <<= 1) {      // suffix scan, 11 steps
        unsigned v0 = (tid + off < HBINS) ? hist[tid + off] : 0u;
        unsigned v1 = (tid + NT + off < HBINS) ? hist[tid + NT + off] : 0u;
        __syncthreads();
        hist[tid] += v0;
        hist[tid + NT] += v1;
        __syncthreads();
    }
    {
        unsigned s0 = hist[tid];
        unsigned s0n = (tid + 1 < HBINS) ? hist[tid + 1] : 0u;
        if (s0 >= TSAMP && s0n < TSAMP) s_bin = tid;
        unsigned s1 = hist[tid + NT];
        unsigned s1n = (tid + NT + 1 < HBINS) ? hist[tid + NT + 1] : 0u;
        if (s1 >= TSAMP && s1n < TSAMP) s_bin = tid + NT;
    }
    __syncthreads();
    const unsigned thr_bits = (unsigned)s_bin << 21;
    const float thrf = __uint_as_float(unflipf(thr_bits));

    // ---------------- phase 2: free-running stream, no mid barriers ----------------
    #pragma unroll 4
    for (int base = tid * 4; base < NN; base += NT * 4) {
        float4 v = __ldcs(reinterpret_cast<const float4*>(Lp + base));
        if (v.x >= thrf) append_key(buf, &s_count, flipf(__float_as_uint(v.x)), base);
        if (v.y >= thrf) append_key(buf, &s_count, flipf(__float_as_uint(v.y)), base + 1);
        if (v.z >= thrf) append_key(buf, &s_count, flipf(__float_as_uint(v.z)), base + 2);
        if (v.w >= thrf) append_key(buf, &s_count, flipf(__float_as_uint(v.w)), base + 3);
    }
    __syncthreads();
    int m = s_count;

    // ---------------- overflow fallback: old adaptive algorithm ----------------
    if (m > CAP) {
        if (tid == 0) s_count = 0;
        __syncthreads();
        unsigned thr = 0u;
        for (int g = 0; g < 20; ++g) {
            int base = g * GSIZE + tid * 4;
            if (base < NN) {
                float4 v = *reinterpret_cast<const float4*>(Lp + base);
                unsigned ubs[4] = {flipf(__float_as_uint(v.x)), flipf(__float_as_uint(v.y)),
                                   flipf(__float_as_uint(v.z)), flipf(__float_as_uint(v.w))};
                #pragma unroll
                for (int e = 0; e < 4; ++e)
                    if (ubs[e] >= thr) append_key(buf, &s_count, ubs[e], base + e);
            }
            __syncthreads();
            if (g == 0 || s_count > CAP - GSIZE) {
                int n = min(s_count, CAP);
                run_select(buf, lst, hist, sc, n, TSEL);
                int mm = min(sc[3], LISTCAP);
                for (int i = tid; i < mm; i += NT) buf[i] = lst[i];
                __syncthreads();
                if (tid == 0) s_count = mm;
                __syncthreads();
                thr = sc[2] ? (((unsigned)sc[0] << 21) | ((unsigned)sc[1] << 10))
                            : ((unsigned)sc[0] << 21);
            }
        }
        int n = min(s_count, CAP);
        run_select(buf, lst, hist, sc, n, TSEL);
        m = min(sc[3], LISTCAP);
        for (int i = tid; i < m; i += NT) buf[i] = lst[i];
        __syncthreads();
    }

    // ---------------- phase 3: sigmoid keys + exact rank + write ----------------
    for (int i = tid; i < m; i += NT) {
        unsigned long long k = buf[i];
        unsigned u = (unsigned)(k >> 32);
        unsigned idx = (unsigned)k;
        float s = sigmoid_ref(__uint_as_float(unflipf(u)));
        buf[i] = ((unsigned long long)__float_as_uint(s) << 32) |
                 (unsigned)(0xFFFFFFFFu - idx);
    }
    __syncthreads();

    for (int i = tid; i < m; i += NT) {
        unsigned long long k = buf[i];
        int r = 0;
        for (int j = 0; j < m; ++j) r += (buf[j] > k) ? 1 : 0;
        if (r < TOPK) {
            unsigned idx = 0xFFFFFFFFu - (unsigned)k;
            float s = __uint_as_float((unsigned)(k >> 32));
            int q = (int)(idx / NC);
            int c = (int)(idx - (unsigned)q * NC);
            size_t o = (size_t)b * TOPK + (size_t)r;
            out[o] = (float)c;                                   // labels
            float4 bx = *reinterpret_cast<const float4*>(
                boxes + ((size_t)b * NQ + (size_t)q) * 4);
            float4 xy;
            xy.x = bx.x - 0.5f * bx.z;
            xy.y = bx.y - 0.5f * bx.w;
            xy.z = bx.x + 0.5f * bx.z;
            xy.w = bx.y + 0.5f * bx.w;
            *reinterpret_cast<float4*>(out + (size_t)NB * TOPK + o * 4) = xy;  // boxes
            out[(size_t)NB * TOPK * 5 + o] = s;                  // scores
        }
    }
}

extern "C" void kernel_launch(void* const* d_in, const int* in_sizes, int n_in,
                              void* d_out, int out_size) {
    const float* logits = (const float*)d_in[0];
    const float* boxes = (const float*)d_in[1];
    size_t smem = (size_t)CAP * 8 + (size_t)LISTCAP * 8 + (size_t)HBINS * 4; // 73728 B
    cudaFuncSetAttribute(postproc_kernel,
                         cudaFuncAttributeMaxDynamicSharedMemorySize, (int)smem);
    postproc_kernel<<<NB, NT, smem>>>(logits, boxes, (float*)d_out);
}

// round 3
// speedup vs baseline: 4.1894x; 4.1894x over previous
#include <cuda_runtime.h>

#define NB 256
#define NQ 1000
#define NC 80
#define NN 80000          // NQ * NC per batch
#define TOPK 300
#define NT 1024
#define GSIZE 4096        // fallback group size
#define CAP 6144          // candidate buffer entries (u64)
#define LISTCAP 2048
#define HBINS 2048
#define TSAMP 64          // sample-rank target for streaming threshold
#define TSEL 384          // final selection rank (slack over 300)

// ---------- monotone float<->uint mapping (handles negatives) ----------
__device__ __forceinline__ unsigned flipf(unsigned b) {
    return (b & 0x80000000u) ? ~b : (b | 0x80000000u);
}
__device__ __forceinline__ unsigned unflipf(unsigned u) {
    return (u & 0x80000000u) ? (u & 0x7FFFFFFFu) : ~u;
}

// ---------- sigmoid matching XLA: logistic(x) = 0.5 + 0.5*tanh(0.5*x) ----------
__device__ __forceinline__ float sigmoid_ref(float x) {
    float hx = __fmul_rn(0.5f, x);
    float ax = fabsf(hx);
    float xc = fminf(fmaxf(hx, -9.0f), 9.0f);
    float x2 = __fmul_rn(xc, xc);
    float p = -2.76076847742355e-16f;
    p = fmaf(x2, p, 2.00018790482477e-13f);
    p = fmaf(x2, p, -8.60467152213735e-11f);
    p = fmaf(x2, p, 5.12229709037114e-08f);
    p = fmaf(x2, p, 1.48572235717979e-05f);
    p = fmaf(x2, p, 6.37261928875436e-04f);
    p = fmaf(x2, p, 4.89352455891786e-03f);
    p = __fmul_rn(xc, p);
    float q = 1.19825839466702e-06f;
    q = fmaf(x2, q, 1.18534705686654e-04f);
    q = fmaf(x2, q, 2.26843463243900e-03f);
    q = fmaf(x2, q, 4.89352518554385e-03f);
    float t = __fdiv_rn(p, q);
    t = (ax < 4e-4f) ? hx : t;
    return __fadd_rn(__fmul_rn(0.5f, t), 0.5f);
}

// ---------- warp-aggregated append ----------
__device__ __forceinline__ void append_key(unsigned long long* buf, int* cnt,
                                           unsigned ub, unsigned idx) {
    unsigned long long key = ((unsigned long long)ub << 32) | idx;
    unsigned mask = __activemask();
    int lane = threadIdx.x & 31;
    int leader = __ffs(mask) - 1;
    int pos = 0;
    if (lane == leader) pos = atomicAdd(cnt, __popc(mask));
    pos = __shfl_sync(mask, pos, leader) + __popc(mask & ((1u << lane) - 1u));
    if (pos < CAP) buf[pos] = key;
}

// ---------- fast block suffix scan over 2048 bins (shfl-based, 2 barriers) ----------
// Precondition: a __syncthreads() already separates histogram writes from this call.
__device__ __forceinline__ void suffix_scan(unsigned* hist, unsigned* wsum) {
    const int tid = threadIdx.x;
    const int lane = tid & 31;
    const int w = tid >> 5;
    unsigned x0 = hist[2047 - 2 * tid];
    unsigned x1 = hist[2046 - 2 * tid];
    unsigned s = x0 + x1;
    unsigned incl = s;
    #pragma unroll
    for (int o = 1; o < 32; o <<= 1) {
        unsigned v = __shfl_up_sync(0xFFFFFFFFu, incl, o);
        if (lane >= o) incl += v;
    }
    if (lane == 31) wsum[w] = incl;
    unsigned excl_lane = incl - s;
    __syncthreads();
    if (tid < 32) {
        unsigned v = wsum[tid];
        unsigned wincl = v;
        #pragma unroll
        for (int o = 1; o < 32; o <<= 1) {
            unsigned t2 = __shfl_up_sync(0xFFFFFFFFu, wincl, o);
            if (tid >= o) wincl += t2;
        }
        wsum[tid] = wincl - v;   // exclusive warp offsets
    }
    __syncthreads();
    unsigned excl = wsum[w] + excl_lane;
    hist[2047 - 2 * tid] = excl + x0;          // suffix(2047-2t)
    hist[2046 - 2 * tid] = excl + x0 + x1;     // suffix(2046-2t)
    __syncthreads();
}

// ---------- histogram radix-select: keeps >= target best keys of buf[0..n) in lst ----------
// sc[0]=B, sc[1]=B2, sc[2]=refined, sc[3]=gathered count, sc[4]=nAbove
__device__ void run_select(unsigned long long* buf, unsigned long long* lst,
                           unsigned* hist, unsigned* wsum, int* sc, int n, int target) {
    const int tid = threadIdx.x;
    if (n <= target) {
        if (tid == 0) { sc[0] = 0; sc[1] = 0; sc[2] = 0; sc[3] = n; }
        __syncthreads();
        for (int i = tid; i < n; i += NT) lst[i] = buf[i];
        __syncthreads();
        return;
    }
    hist[tid] = 0; hist[tid + NT] = 0;
    __syncthreads();
    for (int i = tid; i < n; i += NT)
        atomicAdd(&hist[(unsigned)(buf[i] >> 53)], 1u);
    __syncthreads();
    suffix_scan(hist, wsum);
    {
        unsigned s0 = hist[tid];
        unsigned s0n = (tid + 1 < HBINS) ? hist[tid + 1] : 0u;
        if (s0 >= (unsigned)target && s0n < (unsigned)target) { sc[0] = tid; sc[4] = (int)s0n; }
        unsigned s1 = hist[tid + NT];
        unsigned s1n = (tid + NT + 1 < HBINS) ? hist[tid + NT + 1] : 0u;
        if (s1 >= (unsigned)target && s1n < (unsigned)target) { sc[0] = tid + NT; sc[4] = (int)s1n; }
    }
    if (tid == 0) { sc[2] = 0; sc[3] = 0; }
    __syncthreads();
    const int B = sc[0];
    const int nAbove = sc[4];
    const int selcount = (int)hist[B];
    int refined = 0, B2 = 0;
    if (selcount > 1024) {                 // refine within bin B on next 11 bits
        __syncthreads();
        hist[tid] = 0; hist[tid + NT] = 0;
        __syncthreads();
        for (int i = tid; i < n; i += NT) {
            unsigned long long k = buf[i];
            if ((unsigned)(k >> 53) == (unsigned)B)
                atomicAdd(&hist[(unsigned)(k >> 42) & 0x7FFu], 1u);
        }
        __syncthreads();
        suffix_scan(hist, wsum);
        int extra = target - nAbove;
        {
            unsigned s0 = hist[tid];
            unsigned s0n = (tid + 1 < HBINS) ? hist[tid + 1] : 0u;
            if (s0 >= (unsigned)extra && s0n < (unsigned)extra) sc[1] = tid;
            unsigned s1 = hist[tid + NT];
            unsigned s1n = (tid + NT + 1 < HBINS) ? hist[tid + NT + 1] : 0u;
            if (s1 >= (unsigned)extra && s1n < (unsigned)extra) sc[1] = tid + NT;
        }
        if (tid == 0) sc[2] = 1;
        __syncthreads();
        refined = 1;
        B2 = sc[1];
    }
    for (int i = tid; i < n; i += NT) {
        unsigned long long k = buf[i];
        unsigned bin = (unsigned)(k >> 53);
        bool sel = (bin > (unsigned)B) ||
                   (bin == (unsigned)B &&
                    (!refined || (((unsigned)(k >> 42) & 0x7FFu) >= (unsigned)B2)));
        if (sel) {
            int p = atomicAdd(&sc[3], 1);
            if (p < LISTCAP) lst[p] = k;
        }
    }
    __syncthreads();
}

extern "C" __global__ void __launch_bounds__(NT, 2)
postproc_kernel(const float* __restrict__ logits,
                const float* __restrict__ boxes,
                float* __restrict__ out) {
    extern __shared__ unsigned char smem_raw[];
    unsigned long long* buf = reinterpret_cast<unsigned long long*>(smem_raw);
    unsigned long long* lst = buf + CAP;
    unsigned* hist = reinterpret_cast<unsigned*>(lst + LISTCAP);
    __shared__ unsigned wsum[32];
    __shared__ int s_count;
    __shared__ int s_bin;
    __shared__ int sc[5];

    const int tid = threadIdx.x;
    const int b = blockIdx.x;
    const float* Lp = logits + (size_t)b * NN;

    // ---------------- phase 1: threshold from first 4096 elements ----------------
    hist[tid] = 0; hist[tid + NT] = 0;
    if (tid == 0) { s_count = 0; s_bin = 0; }
    __syncthreads();
    {
        float4 v = *reinterpret_cast<const float4*>(Lp + tid * 4);
        atomicAdd(&hist[flipf(__float_as_uint(v.x)) >> 21], 1u);
        atomicAdd(&hist[flipf(__float_as_uint(v.y)) >> 21], 1u);
        atomicAdd(&hist[flipf(__float_as_uint(v.z)) >> 21], 1u);
        atomicAdd(&hist[flipf(__float_as_uint(v.w)) >> 21], 1u);
    }
    __syncthreads();
    suffix_scan(hist, wsum);
    {
        unsigned s0 = hist[tid];
        unsigned s0n = (tid + 1 < HBINS) ? hist[tid + 1] : 0u;
        if (s0 >= TSAMP && s0n < TSAMP) s_bin = tid;
        unsigned s1 = hist[tid + NT];
        unsigned s1n = (tid + NT + 1 < HBINS) ? hist[tid + NT + 1] : 0u;
        if (s1 >= TSAMP && s1n < TSAMP) s_bin = tid + NT;
    }
    __syncthreads();
    const float thrf = __uint_as_float(unflipf((unsigned)s_bin << 21));

    // ---------------- phase 2: free-running stream, no mid barriers ----------------
    #pragma unroll 5
    for (int base = tid * 4; base < NN; base += NT * 4) {
        float4 v = __ldcs(reinterpret_cast<const float4*>(Lp + base));
        if (v.x >= thrf) append_key(buf, &s_count, flipf(__float_as_uint(v.x)), base);
        if (v.y >= thrf) append_key(buf, &s_count, flipf(__float_as_uint(v.y)), base + 1);
        if (v.z >= thrf) append_key(buf, &s_count, flipf(__float_as_uint(v.z)), base + 2);
        if (v.w >= thrf) append_key(buf, &s_count, flipf(__float_as_uint(v.w)), base + 3);
    }
    __syncthreads();
    int m = s_count;

    // ---------------- overflow fallback (never taken on normal data) ----------------
    if (m > CAP) {
        if (tid == 0) s_count = 0;
        __syncthreads();
        unsigned thr = 0u;
        for (int g = 0; g < 20; ++g) {
            int base = g * GSIZE + tid * 4;
            if (base < NN) {
                float4 v = *reinterpret_cast<const float4*>(Lp + base);
                unsigned ubs[4] = {flipf(__float_as_uint(v.x)), flipf(__float_as_uint(v.y)),
                                   flipf(__float_as_uint(v.z)), flipf(__float_as_uint(v.w))};
                #pragma unroll
                for (int e = 0; e < 4; ++e)
                    if (ubs[e] >= thr) append_key(buf, &s_count, ubs[e], base + e);
            }
            __syncthreads();
            if (g == 0 || s_count > CAP - GSIZE) {
                int n = min(s_count, CAP);
                run_select(buf, lst, hist, wsum, sc, n, TSEL);
                int mm = min(sc[3], LISTCAP);
                for (int i = tid; i < mm; i += NT) buf[i] = lst[i];
                __syncthreads();
                if (tid == 0) s_count = mm;
                __syncthreads();
                thr = sc[2] ? (((unsigned)sc[0] << 21) | ((unsigned)sc[1] << 10))
                            : ((unsigned)sc[0] << 21);
            }
        }
        m = min(s_count, CAP);
    }

    // ---------------- phase 3: prune to ~TSEL, sigmoid keys, exact rank ----------------
    run_select(buf, lst, hist, wsum, sc, m, TSEL);
    int msel = min(sc[3], LISTCAP);

    for (int i = tid; i < msel; i += NT) {
        unsigned long long k = lst[i];
        unsigned u = (unsigned)(k >> 32);
        unsigned idx = (unsigned)k;
        float s = sigmoid_ref(__uint_as_float(unflipf(u)));
        lst[i] = ((unsigned long long)__float_as_uint(s) << 32) |
                 (unsigned)(0xFFFFFFFFu - idx);
    }
    __syncthreads();

    for (int i = tid; i < msel; i += NT) {
        unsigned long long k = lst[i];
        int r = 0;
        for (int j = 0; j < msel; ++j) r += (lst[j] > k) ? 1 : 0;
        if (r < TOPK) {
            unsigned idx = 0xFFFFFFFFu - (unsigned)k;
            float s = __uint_as_float((unsigned)(k >> 32));
            int q = (int)(idx / NC);
            int c = (int)(idx - (unsigned)q * NC);
            size_t o = (size_t)b * TOPK + (size_t)r;
            out[o] = (float)c;                                   // labels
            float4 bx = *reinterpret_cast<const float4*>(
                boxes + ((size_t)b * NQ + (size_t)q) * 4);
            float4 xy;
            xy.x = bx.x - 0.5f * bx.z;
            xy.y = bx.y - 0.5f * bx.w;
            xy.z = bx.x + 0.5f * bx.z;
            xy.w = bx.y + 0.5f * bx.w;
            *reinterpret_cast<float4*>(out + (size_t)NB * TOPK + o * 4) = xy;  // boxes
            out[(size_t)NB * TOPK * 5 + o] = s;                  // scores
        }
    }
}

extern "C" void kernel_launch(void* const* d_in, const int* in_sizes, int n_in,
                              void* d_out, int out_size) {
    const float* logits = (const float*)d_in[0];
    const float* boxes = (const float*)d_in[1];
    size_t smem = (size_t)CAP * 8 + (size_t)LISTCAP * 8 + (size_t)HBINS * 4; // 73728 B
    cudaFuncSetAttribute(postproc_kernel,
                         cudaFuncAttributeMaxDynamicSharedMemorySize, (int)smem);
    postproc_kernel<<<NB, NT, smem>>>(logits, boxes, (float*)d_out);
}